// round 13
// baseline (speedup 1.0000x reference)
#include <cuda_runtime.h>
#include <math.h>

#define Bc 4
#define Tc 2048
#define Ec 64
#define Hc 8
#define QLc 6
#define BHc (Bc*Hc)
#define CAP 416

// S = {0..7, 9, 13, 21, 37}: member(r,c) <=> ((r-c) mod 64) in S  (sparse rows)
#define REMMASK (0xFFull | (1ull<<9) | (1ull<<13) | (1ull<<21) | (1ull<<37))

__device__ float g_Q[BHc*Tc*Ec];     // [b,h,t,e]
__device__ float g_K[BHc*Tc*Ec];
__device__ float g_V[BHc*Tc*Ec];
__device__ float g_ATT[BHc*Tc*Ec];
__device__ float g_Wt[384*1024];     // transposed Wqk: [kk][ch]
__device__ unsigned short g_cols[Tc*CAP];
__device__ int g_cnt[Tc];

// ---- f32x2 packed FMA ----
__device__ __forceinline__ float2 ffma2(float2 a, float2 b, float2 c) {
    float2 d;
    asm("fma.rn.f32x2 %0, %1, %2, %3;"
        : "=l"(*(unsigned long long*)&d)
        : "l"(*(unsigned long long*)&a),
          "l"(*(unsigned long long*)&b),
          "l"(*(unsigned long long*)&c));
    return d;
}
__device__ __forceinline__ int rank_of(int s) {
    return __popcll(REMMASK & ((1ull << s) - 1ull));
}

// ===========================================================================
// Fat prep: blocks [0,1024) proj_v | [1024,1408) wt_transpose |
// [1408,1416) build_cols.
// ===========================================================================
__global__ __launch_bounds__(256) void fat_prep(const float* __restrict__ x,
                                                const float* __restrict__ Wv,
                                                const float* __restrict__ bv,
                                                const float* __restrict__ Wqk) {
    int bid = blockIdx.x;
    int tid = threadIdx.x;
    if (bid < 1024) {
        __shared__ float xs[8][64];
        int bt0 = bid * 8;
        if (tid < 128) {
            int m = tid >> 4, i = (tid << 2) & 63;
            *(float4*)&xs[m][i] = *(const float4*)(x + (size_t)(bt0 + m) * Ec + i);
        }
        __syncthreads();
        int nc = tid * 2;
        float2 acc[8];
        #pragma unroll
        for (int m = 0; m < 8; m++) acc[m] = make_float2(0.f, 0.f);
        for (int i = 0; i < 64; i++) {
            float2 w2 = *(const float2*)(Wv + (size_t)i * 512 + nc);
            #pragma unroll
            for (int m = 0; m < 8; m++) {
                float xm = xs[m][i];
                acc[m] = ffma2(make_float2(xm, xm), w2, acc[m]);
            }
        }
        float2 b2 = *(const float2*)(bv + nc);
        int h = nc >> 6, e = nc & 63;
        int b = bt0 / Tc;
        #pragma unroll
        for (int m = 0; m < 8; m++) {
            int t = (bt0 & (Tc - 1)) + m;
            *(float2*)(g_V + (((size_t)b * Hc + h) * Tc + t) * Ec + e) =
                make_float2(acc[m].x + b2.x, acc[m].y + b2.y);
        }
    } else if (bid < 1408) {
        __shared__ float tile[32][33];
        int b2 = bid - 1024;
        int ch0 = (b2 & 31) * 32;
        int kk0 = (b2 >> 5) * 32;
        int lx = tid & 31, ly = tid >> 5;
        #pragma unroll
        for (int k = 0; k < 4; k++)
            tile[ly + 8 * k][lx] = Wqk[(size_t)(ch0 + ly + 8 * k) * 384 + kk0 + lx];
        __syncthreads();
        #pragma unroll
        for (int k = 0; k < 4; k++)
            g_Wt[(size_t)(kk0 + ly + 8 * k) * 1024 + ch0 + lx] = tile[lx][ly + 8 * k];
    } else {
        int row = (bid - 1408) * 256 + tid;
        if (row >= Tc) return;
        const int log_l = 6, sub = 64;
        unsigned short* out = g_cols + row * CAP;
        if ((Tc / sub) * 2 * log_l > row) {       // dense causal
            for (int j = 0; j <= row; j++) out[j] = (unsigned short)j;
            g_cnt[row] = row + 1;
            return;
        }
        unsigned short tmp[CAP];
        int cnt = 0;
        int index = row;
        while (index >= 0) {
            if (index - log_l + 1 < 0) {
                for (int j = index - 1; j >= 0; j--) tmp[cnt++] = (unsigned short)j;
                break;
            }
            for (int j = index; j >= index - log_l + 1; j--)
                tmp[cnt++] = (unsigned short)j;
            for (int i = 0; i < log_l; i++) {
                int ni = index - log_l + 1 - (1 << i);
                if (index - ni <= sub && ni >= 0) tmp[cnt++] = (unsigned short)ni;
            }
            index -= sub;
        }
        for (int j = 0; j < cnt; j++) out[j] = tmp[cnt - 1 - j];
        g_cnt[row] = cnt;
    }
}

// ===========================================================================
// Causal conv1d QK projection: 64t x 64ch block GEMM (unchanged)
// ===========================================================================
__global__ __launch_bounds__(256) void proj_qk2(const float* __restrict__ x,
                                                const float* __restrict__ bqk) {
    __shared__ float XsT[64][72];
    __shared__ float Wc[96][64];
    int b   = blockIdx.z;
    int ch0 = blockIdx.y * 64;
    int t0  = blockIdx.x * 64;
    int tid = threadIdx.x;
    int tx = tid & 15;
    int cx = tid >> 4;

    for (int idx = tid; idx < 69 * 16; idx += 256) {
        int s = idx >> 4, i4 = (idx & 15) * 4;
        int t = t0 - 5 + s;
        float4 v = (t >= 0) ? *(const float4*)(x + ((size_t)b * Tc + t) * Ec + i4)
                            : make_float4(0.f, 0.f, 0.f, 0.f);
        XsT[i4 + 0][s] = v.x; XsT[i4 + 1][s] = v.y;
        XsT[i4 + 2][s] = v.z; XsT[i4 + 3][s] = v.w;
    }

    float2 acc2[4][2];
    #pragma unroll
    for (int tt = 0; tt < 4; tt++) { acc2[tt][0] = make_float2(0.f,0.f); acc2[tt][1] = make_float2(0.f,0.f); }

    for (int ic = 0; ic < 4; ic++) {
        __syncthreads();
        for (int idx = tid; idx < 96 * 16; idx += 256) {
            int row = idx >> 4, c4 = (idx & 15) * 4;
            *(float4*)&Wc[row][c4] =
                *(const float4*)(g_Wt + (size_t)(ic * 96 + row) * 1024 + ch0 + c4);
        }
        __syncthreads();
        #pragma unroll 4
        for (int ii = 0; ii < 16; ii++) {
            float4 A  = *(float4*)&XsT[ic * 16 + ii][tx * 4];
            float4 Bf = *(float4*)&XsT[ic * 16 + ii][tx * 4 + 4];
            float c8  = XsT[ic * 16 + ii][tx * 4 + 8];
            float win[9] = {A.x, A.y, A.z, A.w, Bf.x, Bf.y, Bf.z, Bf.w, c8};
            #pragma unroll
            for (int j = 0; j < 6; j++) {
                float4 w4 = *(float4*)&Wc[ii * 6 + j][cx * 4];
                float2 wp0 = make_float2(w4.x, w4.y);
                float2 wp1 = make_float2(w4.z, w4.w);
                #pragma unroll
                for (int tt = 0; tt < 4; tt++) {
                    float xv = win[j + tt];
                    float2 xb = make_float2(xv, xv);
                    acc2[tt][0] = ffma2(xb, wp0, acc2[tt][0]);
                    acc2[tt][1] = ffma2(xb, wp1, acc2[tt][1]);
                }
            }
        }
    }
    int ch = ch0 + cx * 4;
    float4 b4 = *(const float4*)(bqk + ch);
    int hh = (ch & 511) >> 6, e0 = ch & 63;
    float* base = (ch < 512 ? g_Q : g_K) + ((size_t)b * Hc + hh) * Tc * Ec + e0;
    #pragma unroll
    for (int tt = 0; tt < 4; tt++) {
        int t = t0 + tx * 4 + tt;
        float4 o = make_float4(acc2[tt][0].x + b4.x, acc2[tt][0].y + b4.y,
                               acc2[tt][1].x + b4.z, acc2[tt][1].y + b4.w);
        *(float4*)(base + (size_t)t * Ec) = o;
    }
}

// ===========================================================================
// Dense attention (rows < 384): GEMM-tiled; heavy tiles scheduled first.
// ===========================================================================
#define SCD(r,c) dsm[(r)*385 + (c)]
#define QSd(r,e) dsm[12320 + (r)*65 + (e)]
#define KTd(c,e) dsm[14400 + (c)*65 + (e)]

__global__ __launch_bounds__(256) void dense_attn(float* __restrict__ wout_base) {
    extern __shared__ float dsm[];
    int rt = 11 - blockIdx.x;       // heavy tiles (large r0) first
    int bh = blockIdx.y;
    int r0 = rt * 32;
    int tid = threadIdx.x;
    int ty = tid >> 5, lane = tid & 31;
    int ntiles = (r0 + 31) / 64 + 1;

    for (int idx = tid; idx < 32 * 385; idx += 256) dsm[idx] = 0.f;

    const float* Qb = g_Q + ((size_t)bh * Tc + r0) * Ec;
    for (int idx = tid; idx < 32 * 16; idx += 256) {
        int r = idx >> 4, e4 = (idx & 15) * 4;
        float4 v = *(const float4*)(Qb + (size_t)r * Ec + e4);
        QSd(r, e4 + 0) = v.x; QSd(r, e4 + 1) = v.y;
        QSd(r, e4 + 2) = v.z; QSd(r, e4 + 3) = v.w;
    }

    const float* Kb = g_K + (size_t)bh * Tc * Ec;
    for (int kt = 0; kt < ntiles; kt++) {
        __syncthreads();
        for (int idx = tid; idx < 64 * 16; idx += 256) {
            int c = idx >> 4, e4 = (idx & 15) * 4;
            float4 v = *(const float4*)(Kb + (size_t)(kt * 64 + c) * Ec + e4);
            KTd(c, e4 + 0) = v.x; KTd(c, e4 + 1) = v.y;
            KTd(c, e4 + 2) = v.z; KTd(c, e4 + 3) = v.w;
        }
        __syncthreads();
        float acc[4][2];
        #pragma unroll
        for (int i = 0; i < 4; i++) { acc[i][0] = 0.f; acc[i][1] = 0.f; }
        #pragma unroll 4
        for (int e = 0; e < 64; e++) {
            float kv0 = KTd(lane, e), kv1 = KTd(lane + 32, e);
            #pragma unroll
            for (int i = 0; i < 4; i++) {
                float qv = QSd(ty * 4 + i, e);
                acc[i][0] += qv * kv0;
                acc[i][1] += qv * kv1;
            }
        }
        #pragma unroll
        for (int i = 0; i < 4; i++) {
            int rl = ty * 4 + i, r = r0 + rl;
            int c0 = kt * 64 + lane, c1 = c0 + 32;
            if (c0 <= r) SCD(rl, c0) = acc[i][0] * 0.125f;
            if (c1 <= r) SCD(rl, c1) = acc[i][1] * 0.125f;
        }
    }
    __syncthreads();

    #pragma unroll
    for (int it = 0; it < 4; it++) {
        int rl = it * 8 + ty, r = r0 + rl, n = r + 1;
        float m = -1e30f;
        for (int c = lane; c < n; c += 32) m = fmaxf(m, SCD(rl, c));
        #pragma unroll
        for (int off = 16; off; off >>= 1)
            m = fmaxf(m, __shfl_xor_sync(0xffffffffu, m, off));
        float sum = 0.f;
        for (int c = lane; c < n; c += 32) {
            float e = __expf(SCD(rl, c) - m);
            SCD(rl, c) = e;
            sum += e;
        }
        #pragma unroll
        for (int off = 16; off; off >>= 1)
            sum += __shfl_xor_sync(0xffffffffu, sum, off);
        float inv = __fdividef(1.f, sum);
        float* wrow = wout_base + ((size_t)bh * Tc + r) * Tc;
        for (int c = lane; c < Tc; c += 32) {
            float v = 0.f;
            if (c < n) { v = SCD(rl, c) * inv; SCD(rl, c) = v; }
            __stwt(&wrow[c], v);
        }
    }
    __syncthreads();

    const float* Vb = g_V + (size_t)bh * Tc * Ec;
    float oacc[4][2];
    #pragma unroll
    for (int i = 0; i < 4; i++) { oacc[i][0] = 0.f; oacc[i][1] = 0.f; }
    for (int kt = 0; kt < ntiles; kt++) {
        __syncthreads();
        for (int idx = tid; idx < 64 * 16; idx += 256) {
            int c = idx >> 4, e4 = (idx & 15) * 4;
            float4 v = *(const float4*)(Vb + (size_t)(kt * 64 + c) * Ec + e4);
            KTd(c, e4 + 0) = v.x; KTd(c, e4 + 1) = v.y;
            KTd(c, e4 + 2) = v.z; KTd(c, e4 + 3) = v.w;
        }
        __syncthreads();
        #pragma unroll 4
        for (int c = 0; c < 64; c++) {
            float v0 = KTd(c, lane), v1 = KTd(c, lane + 32);
            #pragma unroll
            for (int i = 0; i < 4; i++) {
                float wg = SCD(ty * 4 + i, kt * 64 + c);
                oacc[i][0] += wg * v0;
                oacc[i][1] += wg * v1;
            }
        }
    }
    #pragma unroll
    for (int i = 0; i < 4; i++) {
        float* dst = g_ATT + ((size_t)bh * Tc + r0 + ty * 4 + i) * Ec;
        dst[lane] = oacc[i][0];
        dst[lane + 32] = oacc[i][1];
    }
}

// ===========================================================================
// Sparse attention (rows >= 384): one warp per row; score loop unroll-16
// (8 LDG.128 in flight) + early-out zero writes.
// ===========================================================================
__global__ __launch_bounds__(256) void attn_sparse(float* __restrict__ wout_base) {
    __shared__ float sc[8][CAP];
    int w = threadIdx.x >> 5;
    int lane = threadIdx.x & 31;
    int sub = lane & 7;
    int grp = lane >> 3;
    int r = 2047 - (blockIdx.x * 8 + w);
    int bh = blockIdx.y;

    const float* Qrow = g_Q + ((size_t)bh * Tc + r) * Ec;
    float4 qa4 = *(const float4*)(Qrow + sub * 4);
    float4 qb4 = *(const float4*)(Qrow + 32 + sub * 4);
    float2 qa = make_float2(qa4.x, qa4.y), qb = make_float2(qa4.z, qa4.w);
    float2 qc = make_float2(qb4.x, qb4.y), qd = make_float2(qb4.z, qb4.w);

    int cnt = g_cnt[r];
    const unsigned short* cl = g_cols + r * CAP;
    const float* Kb = g_K + (size_t)bh * Tc * Ec;
    const float2 zero2 = make_float2(0.f, 0.f);

    float m = -1e30f;
    int j0 = 0;
    // unroll-16: 8 LDG.128 in flight per thread
    for (; j0 + 16 <= cnt; j0 += 16) {
        int cA = cl[j0 + grp],      cB = cl[j0 + 4 + grp];
        int cC = cl[j0 + 8 + grp],  cD = cl[j0 + 12 + grp];
        const float* kA = Kb + (size_t)cA * Ec;
        const float* kB = Kb + (size_t)cB * Ec;
        const float* kC = Kb + (size_t)cC * Ec;
        const float* kD = Kb + (size_t)cD * Ec;
        float4 a0 = *(const float4*)(kA + sub * 4);
        float4 a1 = *(const float4*)(kA + 32 + sub * 4);
        float4 b0 = *(const float4*)(kB + sub * 4);
        float4 b1 = *(const float4*)(kB + 32 + sub * 4);
        float4 c0 = *(const float4*)(kC + sub * 4);
        float4 c1 = *(const float4*)(kC + 32 + sub * 4);
        float4 d0 = *(const float4*)(kD + sub * 4);
        float4 d1 = *(const float4*)(kD + 32 + sub * 4);
        float2 sA = ffma2(qa, make_float2(a0.x, a0.y), zero2);
        float2 sB = ffma2(qa, make_float2(b0.x, b0.y), zero2);
        float2 sC = ffma2(qa, make_float2(c0.x, c0.y), zero2);
        float2 sD = ffma2(qa, make_float2(d0.x, d0.y), zero2);
        sA = ffma2(qb, make_float2(a0.z, a0.w), sA);
        sB = ffma2(qb, make_float2(b0.z, b0.w), sB);
        sC = ffma2(qb, make_float2(c0.z, c0.w), sC);
        sD = ffma2(qb, make_float2(d0.z, d0.w), sD);
        sA = ffma2(qc, make_float2(a1.x, a1.y), sA);
        sB = ffma2(qc, make_float2(b1.x, b1.y), sB);
        sC = ffma2(qc, make_float2(c1.x, c1.y), sC);
        sD = ffma2(qc, make_float2(d1.x, d1.y), sD);
        sA = ffma2(qd, make_float2(a1.z, a1.w), sA);
        sB = ffma2(qd, make_float2(b1.z, b1.w), sB);
        sC = ffma2(qd, make_float2(c1.z, c1.w), sC);
        sD = ffma2(qd, make_float2(d1.z, d1.w), sD);
        float pA = sA.x + sA.y, pB = sB.x + sB.y;
        float pC = sC.x + sC.y, pD = sD.x + sD.y;
        #pragma unroll
        for (int off = 4; off; off >>= 1) {
            pA += __shfl_down_sync(0xffffffffu, pA, off);
            pB += __shfl_down_sync(0xffffffffu, pB, off);
            pC += __shfl_down_sync(0xffffffffu, pC, off);
            pD += __shfl_down_sync(0xffffffffu, pD, off);
        }
        if (sub == 0) {
            float vA = pA * 0.125f, vB = pB * 0.125f;
            float vC = pC * 0.125f, vD = pD * 0.125f;
            sc[w][j0 + grp]      = vA;
            sc[w][j0 + 4 + grp]  = vB;
            sc[w][j0 + 8 + grp]  = vC;
            sc[w][j0 + 12 + grp] = vD;
            m = fmaxf(m, fmaxf(fmaxf(vA, vB), fmaxf(vC, vD)));
        }
    }
    for (; j0 + 8 <= cnt; j0 += 8) {
        int cA = cl[j0 + grp];
        int cB = cl[j0 + 4 + grp];
        const float* krA = Kb + (size_t)cA * Ec;
        const float* krB = Kb + (size_t)cB * Ec;
        float4 a0 = *(const float4*)(krA + sub * 4);
        float4 a1 = *(const float4*)(krA + 32 + sub * 4);
        float4 b0 = *(const float4*)(krB + sub * 4);
        float4 b1 = *(const float4*)(krB + 32 + sub * 4);
        float2 sA = ffma2(qa, make_float2(a0.x, a0.y), zero2);
        float2 sB = ffma2(qa, make_float2(b0.x, b0.y), zero2);
        sA = ffma2(qb, make_float2(a0.z, a0.w), sA);
        sB = ffma2(qb, make_float2(b0.z, b0.w), sB);
        sA = ffma2(qc, make_float2(a1.x, a1.y), sA);
        sB = ffma2(qc, make_float2(b1.x, b1.y), sB);
        sA = ffma2(qd, make_float2(a1.z, a1.w), sA);
        sB = ffma2(qd, make_float2(b1.z, b1.w), sB);
        float pA = sA.x + sA.y, pB = sB.x + sB.y;
        #pragma unroll
        for (int off = 4; off; off >>= 1) {
            pA += __shfl_down_sync(0xffffffffu, pA, off);
            pB += __shfl_down_sync(0xffffffffu, pB, off);
        }
        if (sub == 0) {
            float vA = pA * 0.125f, vB = pB * 0.125f;
            sc[w][j0 + grp] = vA;
            sc[w][j0 + 4 + grp] = vB;
            m = fmaxf(m, fmaxf(vA, vB));
        }
    }
    for (; j0 < cnt; j0 += 4) {
        int jj = j0 + grp;
        int c = cl[jj < cnt ? jj : cnt - 1];
        const float* krow = Kb + (size_t)c * Ec;
        float4 ka4 = *(const float4*)(krow + sub * 4);
        float4 kb4 = *(const float4*)(krow + 32 + sub * 4);
        float2 s2 = ffma2(qa, make_float2(ka4.x, ka4.y), zero2);
        s2 = ffma2(qb, make_float2(ka4.z, ka4.w), s2);
        s2 = ffma2(qc, make_float2(kb4.x, kb4.y), s2);
        s2 = ffma2(qd, make_float2(kb4.z, kb4.w), s2);
        float p = s2.x + s2.y;
        p += __shfl_down_sync(0xffffffffu, p, 4);
        p += __shfl_down_sync(0xffffffffu, p, 2);
        p += __shfl_down_sync(0xffffffffu, p, 1);
        float s = p * 0.125f;
        if (sub == 0 && jj < cnt) {
            sc[w][jj] = s;
            m = fmaxf(m, s);
        }
    }
    #pragma unroll
    for (int off = 16; off; off >>= 1)
        m = fmaxf(m, __shfl_xor_sync(0xffffffffu, m, off));
    __syncwarp();

    float sum = 0.f;
    for (int jj = lane; jj < cnt; jj += 32) {
        float e = __expf(sc[w][jj] - m);
        sc[w][jj] = e;
        sum += e;
    }
    #pragma unroll
    for (int off = 16; off; off >>= 1)
        sum += __shfl_xor_sync(0xffffffffu, sum, off);
    float inv = __fdividef(1.f, sum);
    __syncwarp();

    // coalesced full-row weight writes: predicate eval only at/below diagonal
    {
        int jl = r & 63;
        int nch = r >> 6;
        float* wrow = wout_base + ((size_t)bh * Tc + r) * Tc;
        const float4 z4 = make_float4(0.f, 0.f, 0.f, 0.f);
        for (int idx = lane; idx < 512; idx += 32) {
            int c0 = idx * 4;
            if (c0 > r) {                 // entirely above diagonal: pure zero
                __stwt(&((float4*)wrow)[idx], z4);
                continue;
            }
            float4 o = z4;
            #pragma unroll
            for (int jq = 0; jq < 4; jq++) {
                int c = c0 + jq;
                int diff = r - c;
                if (diff >= 0) {
                    int s = diff & 63;
                    if (((REMMASK >> s) & 1ull) && !(jl < 5 && c == jl)) {
                        int k = diff >> 6;
                        int jj = cnt - 1 - 12 * k - rank_of(s)
                                 + ((jl < 5 && k == nch) ? 1 : 0);
                        ((float*)&o)[jq] = sc[w][jj] * inv;
                    }
                }
            }
            __stwt(&((float4*)wrow)[idx], o);
        }
    }

    const float* Vb = g_V + (size_t)bh * Tc * Ec;
    float2 oacc = zero2, oacc2 = zero2;
    int jj = 0;
    for (; jj + 8 <= cnt; jj += 8) {
        float2 v[8];
        #pragma unroll
        for (int u = 0; u < 8; u++)
            v[u] = ((const float2*)(Vb + (size_t)cl[jj + u] * Ec))[lane];
        #pragma unroll
        for (int u = 0; u < 8; u += 2) {
            float w0 = sc[w][jj + u], w1 = sc[w][jj + u + 1];
            oacc  = ffma2(make_float2(w0, w0), v[u], oacc);
            oacc2 = ffma2(make_float2(w1, w1), v[u + 1], oacc2);
        }
    }
    for (; jj < cnt; jj++) {
        float wg = sc[w][jj];
        float2 v2 = ((const float2*)(Vb + (size_t)cl[jj] * Ec))[lane];
        oacc = ffma2(make_float2(wg, wg), v2, oacc);
    }
    float* ar = g_ATT + ((size_t)bh * Tc + r) * Ec;
    ((float2*)ar)[lane] = make_float2((oacc.x + oacc2.x) * inv,
                                      (oacc.y + oacc2.y) * inv);
}

// ===========================================================================
// Output projection: 32bt x 64eo block GEMM (unchanged)
// ===========================================================================
__global__ __launch_bounds__(256) void proj_out2(const float* __restrict__ Wp,
                                                 const float* __restrict__ bp,
                                                 float* __restrict__ out) {
    __shared__ float asT[64][36];
    __shared__ float wp[64][68];
    int bt0 = blockIdx.x * 32;
    int b = bt0 / Tc, t0 = bt0 & (Tc - 1);
    int tid = threadIdx.x;
    int ex = tid & 15;
    int mx = tid >> 4;

    float2 acc2[2][2];
    acc2[0][0] = make_float2(0.f,0.f); acc2[0][1] = make_float2(0.f,0.f);
    acc2[1][0] = make_float2(0.f,0.f); acc2[1][1] = make_float2(0.f,0.f);

    for (int cc = 0; cc < 8; cc++) {
        __syncthreads();
        for (int idx = tid; idx < 32 * 16; idx += 256) {
            int m = idx >> 4, e4 = (idx & 15) * 4;
            float4 v = *(const float4*)(g_ATT +
                (((size_t)b * Hc + cc) * Tc + t0 + m) * Ec + e4);
            asT[e4 + 0][m] = v.x; asT[e4 + 1][m] = v.y;
            asT[e4 + 2][m] = v.z; asT[e4 + 3][m] = v.w;
        }
        for (int idx = tid; idx < 64 * 16; idx += 256) {
            int k = idx >> 4, e4 = (idx & 15) * 4;
            *(float4*)&wp[k][e4] =
                *(const float4*)(Wp + (size_t)(cc * 64 + k) * Ec + e4);
        }
        __syncthreads();
        #pragma unroll 8
        for (int k = 0; k < 64; k++) {
            float2 a2 = *(float2*)&asT[k][mx * 2];
            float4 w4 = *(float4*)&wp[k][ex * 4];
            float2 wp0 = make_float2(w4.x, w4.y);
            float2 wp1 = make_float2(w4.z, w4.w);
            float2 xb0 = make_float2(a2.x, a2.x);
            float2 xb1 = make_float2(a2.y, a2.y);
            acc2[0][0] = ffma2(xb0, wp0, acc2[0][0]);
            acc2[0][1] = ffma2(xb0, wp1, acc2[0][1]);
            acc2[1][0] = ffma2(xb1, wp0, acc2[1][0]);
            acc2[1][1] = ffma2(xb1, wp1, acc2[1][1]);
        }
    }
    float4 bp4 = *(const float4*)(bp + ex * 4);
    #pragma unroll
    for (int u = 0; u < 2; u++) {
        int t = t0 + mx * 2 + u;
        float4 o = make_float4(acc2[u][0].x + bp4.x, acc2[u][0].y + bp4.y,
                               acc2[u][1].x + bp4.z, acc2[u][1].y + bp4.w);
        *(float4*)(out + ((size_t)b * Tc + t) * Ec + ex * 4) = o;
    }
}

// ---------------------------------------------------------------------------
extern "C" void kernel_launch(void* const* d_in, const int* in_sizes, int n_in,
                              void* d_out, int out_size) {
    const float* x    = (const float*)d_in[0];
    const float* Wqk  = (const float*)d_in[1];
    const float* bqk  = (const float*)d_in[2];
    const float* Wv   = (const float*)d_in[3];
    const float* bv   = (const float*)d_in[4];
    const float* Wp   = (const float*)d_in[5];
    const float* bp   = (const float*)d_in[6];
    // d_in[7] (mask) unused: regenerated on-device.

    float* out = (float*)d_out;
    float* weights = out + (size_t)Bc * Tc * Ec;

    const int DENSE_SMEM = (32 * 385 + 32 * 65 + 64 * 65) * 4;   // 74,240 B
    cudaFuncSetAttribute(dense_attn,
                         cudaFuncAttributeMaxDynamicSharedMemorySize, DENSE_SMEM);

    fat_prep<<<1416, 256>>>(x, Wv, bv, Wqk);
    proj_qk2<<<dim3(Tc / 64, 16, Bc), 256>>>(x, bqk);
    dense_attn<<<dim3(12, BHc), 256, DENSE_SMEM>>>(weights);
    attn_sparse<<<dim3(208, BHc), 256>>>(weights);
    proj_out2<<<Bc * Tc / 32, 256>>>(Wp, bp, out);
}

// round 14
// speedup vs baseline: 1.0125x; 1.0125x over previous
#include <cuda_runtime.h>
#include <math.h>

#define Bc 4
#define Tc 2048
#define Ec 64
#define Hc 8
#define QLc 6
#define BHc (Bc*Hc)
#define CAP 416

// S = {0..7, 9, 13, 21, 37}: member(r,c) <=> ((r-c) mod 64) in S  (sparse rows)
#define REMMASK (0xFFull | (1ull<<9) | (1ull<<13) | (1ull<<21) | (1ull<<37))

__device__ float g_Q[BHc*Tc*Ec];     // [b,h,t,e]
__device__ float g_K[BHc*Tc*Ec];
__device__ float g_V[BHc*Tc*Ec];
__device__ float g_ATT[BHc*Tc*Ec];
__device__ float g_Wt[384*1024];     // transposed Wqk: [kk][ch]
__device__ unsigned short g_cols[Tc*CAP];
__device__ int g_cnt[Tc];

// ---- f32x2 packed FMA ----
__device__ __forceinline__ float2 ffma2(float2 a, float2 b, float2 c) {
    float2 d;
    asm("fma.rn.f32x2 %0, %1, %2, %3;"
        : "=l"(*(unsigned long long*)&d)
        : "l"(*(unsigned long long*)&a),
          "l"(*(unsigned long long*)&b),
          "l"(*(unsigned long long*)&c));
    return d;
}
__device__ __forceinline__ int rank_of(int s) {
    return __popcll(REMMASK & ((1ull << s) - 1ull));
}

// ===========================================================================
// Fat prep: blocks [0,1024) proj_v | [1024,1408) wt_transpose |
// [1408,1416) build_cols.
// ===========================================================================
__global__ __launch_bounds__(256) void fat_prep(const float* __restrict__ x,
                                                const float* __restrict__ Wv,
                                                const float* __restrict__ bv,
                                                const float* __restrict__ Wqk) {
    int bid = blockIdx.x;
    int tid = threadIdx.x;
    if (bid < 1024) {
        __shared__ float xs[8][64];
        int bt0 = bid * 8;
        if (tid < 128) {
            int m = tid >> 4, i = (tid << 2) & 63;
            *(float4*)&xs[m][i] = *(const float4*)(x + (size_t)(bt0 + m) * Ec + i);
        }
        __syncthreads();
        int nc = tid * 2;
        float2 acc[8];
        #pragma unroll
        for (int m = 0; m < 8; m++) acc[m] = make_float2(0.f, 0.f);
        for (int i = 0; i < 64; i++) {
            float2 w2 = *(const float2*)(Wv + (size_t)i * 512 + nc);
            #pragma unroll
            for (int m = 0; m < 8; m++) {
                float xm = xs[m][i];
                acc[m] = ffma2(make_float2(xm, xm), w2, acc[m]);
            }
        }
        float2 b2 = *(const float2*)(bv + nc);
        int h = nc >> 6, e = nc & 63;
        int b = bt0 / Tc;
        #pragma unroll
        for (int m = 0; m < 8; m++) {
            int t = (bt0 & (Tc - 1)) + m;
            *(float2*)(g_V + (((size_t)b * Hc + h) * Tc + t) * Ec + e) =
                make_float2(acc[m].x + b2.x, acc[m].y + b2.y);
        }
    } else if (bid < 1408) {
        __shared__ float tile[32][33];
        int b2 = bid - 1024;
        int ch0 = (b2 & 31) * 32;
        int kk0 = (b2 >> 5) * 32;
        int lx = tid & 31, ly = tid >> 5;
        #pragma unroll
        for (int k = 0; k < 4; k++)
            tile[ly + 8 * k][lx] = Wqk[(size_t)(ch0 + ly + 8 * k) * 384 + kk0 + lx];
        __syncthreads();
        #pragma unroll
        for (int k = 0; k < 4; k++)
            g_Wt[(size_t)(kk0 + ly + 8 * k) * 1024 + ch0 + lx] = tile[lx][ly + 8 * k];
    } else {
        int row = (bid - 1408) * 256 + tid;
        if (row >= Tc) return;
        const int log_l = 6, sub = 64;
        unsigned short* out = g_cols + row * CAP;
        if ((Tc / sub) * 2 * log_l > row) {       // dense causal
            for (int j = 0; j <= row; j++) out[j] = (unsigned short)j;
            g_cnt[row] = row + 1;
            return;
        }
        unsigned short tmp[CAP];
        int cnt = 0;
        int index = row;
        while (index >= 0) {
            if (index - log_l + 1 < 0) {
                for (int j = index - 1; j >= 0; j--) tmp[cnt++] = (unsigned short)j;
                break;
            }
            for (int j = index; j >= index - log_l + 1; j--)
                tmp[cnt++] = (unsigned short)j;
            for (int i = 0; i < log_l; i++) {
                int ni = index - log_l + 1 - (1 << i);
                if (index - ni <= sub && ni >= 0) tmp[cnt++] = (unsigned short)ni;
            }
            index -= sub;
        }
        for (int j = 0; j < cnt; j++) out[j] = tmp[cnt - 1 - j];
        g_cnt[row] = cnt;
    }
}

// ===========================================================================
// Causal conv1d QK projection: 64t x 64ch block GEMM (unchanged)
// ===========================================================================
__global__ __launch_bounds__(256) void proj_qk2(const float* __restrict__ x,
                                                const float* __restrict__ bqk) {
    __shared__ float XsT[64][72];
    __shared__ float Wc[96][64];
    int b   = blockIdx.z;
    int ch0 = blockIdx.y * 64;
    int t0  = blockIdx.x * 64;
    int tid = threadIdx.x;
    int tx = tid & 15;
    int cx = tid >> 4;

    for (int idx = tid; idx < 69 * 16; idx += 256) {
        int s = idx >> 4, i4 = (idx & 15) * 4;
        int t = t0 - 5 + s;
        float4 v = (t >= 0) ? *(const float4*)(x + ((size_t)b * Tc + t) * Ec + i4)
                            : make_float4(0.f, 0.f, 0.f, 0.f);
        XsT[i4 + 0][s] = v.x; XsT[i4 + 1][s] = v.y;
        XsT[i4 + 2][s] = v.z; XsT[i4 + 3][s] = v.w;
    }

    float2 acc2[4][2];
    #pragma unroll
    for (int tt = 0; tt < 4; tt++) { acc2[tt][0] = make_float2(0.f,0.f); acc2[tt][1] = make_float2(0.f,0.f); }

    for (int ic = 0; ic < 4; ic++) {
        __syncthreads();
        for (int idx = tid; idx < 96 * 16; idx += 256) {
            int row = idx >> 4, c4 = (idx & 15) * 4;
            *(float4*)&Wc[row][c4] =
                *(const float4*)(g_Wt + (size_t)(ic * 96 + row) * 1024 + ch0 + c4);
        }
        __syncthreads();
        #pragma unroll 4
        for (int ii = 0; ii < 16; ii++) {
            float4 A  = *(float4*)&XsT[ic * 16 + ii][tx * 4];
            float4 Bf = *(float4*)&XsT[ic * 16 + ii][tx * 4 + 4];
            float c8  = XsT[ic * 16 + ii][tx * 4 + 8];
            float win[9] = {A.x, A.y, A.z, A.w, Bf.x, Bf.y, Bf.z, Bf.w, c8};
            #pragma unroll
            for (int j = 0; j < 6; j++) {
                float4 w4 = *(float4*)&Wc[ii * 6 + j][cx * 4];
                float2 wp0 = make_float2(w4.x, w4.y);
                float2 wp1 = make_float2(w4.z, w4.w);
                #pragma unroll
                for (int tt = 0; tt < 4; tt++) {
                    float xv = win[j + tt];
                    float2 xb = make_float2(xv, xv);
                    acc2[tt][0] = ffma2(xb, wp0, acc2[tt][0]);
                    acc2[tt][1] = ffma2(xb, wp1, acc2[tt][1]);
                }
            }
        }
    }
    int ch = ch0 + cx * 4;
    float4 b4 = *(const float4*)(bqk + ch);
    int hh = (ch & 511) >> 6, e0 = ch & 63;
    float* base = (ch < 512 ? g_Q : g_K) + ((size_t)b * Hc + hh) * Tc * Ec + e0;
    #pragma unroll
    for (int tt = 0; tt < 4; tt++) {
        int t = t0 + tx * 4 + tt;
        float4 o = make_float4(acc2[tt][0].x + b4.x, acc2[tt][0].y + b4.y,
                               acc2[tt][1].x + b4.z, acc2[tt][1].y + b4.w);
        *(float4*)(base + (size_t)t * Ec) = o;
    }
}

// ===========================================================================
// Dense attention (rows < 384): 16-row tiles (24 per bh) for wave balance.
// smem: scd[16][385] | Qs[16][65] | Kt[64][65]  (45,440 B)
// ===========================================================================
#define SCD(r,c) dsm[(r)*385 + (c)]
#define QSd(r,e) dsm[6160 + (r)*65 + (e)]
#define KTd(c,e) dsm[7200 + (c)*65 + (e)]

__global__ __launch_bounds__(256) void dense_attn(float* __restrict__ wout_base) {
    extern __shared__ float dsm[];
    int rt = 23 - blockIdx.x;       // heavy tiles first
    int bh = blockIdx.y;
    int r0 = rt * 16;
    int tid = threadIdx.x;
    int ty = tid >> 5, lane = tid & 31;
    int ntiles = (r0 + 15) / 64 + 1;

    for (int idx = tid; idx < 16 * 385; idx += 256) dsm[idx] = 0.f;

    const float* Qb = g_Q + ((size_t)bh * Tc + r0) * Ec;
    for (int idx = tid; idx < 16 * 16; idx += 256) {
        int r = idx >> 4, e4 = (idx & 15) * 4;
        float4 v = *(const float4*)(Qb + (size_t)r * Ec + e4);
        QSd(r, e4 + 0) = v.x; QSd(r, e4 + 1) = v.y;
        QSd(r, e4 + 2) = v.z; QSd(r, e4 + 3) = v.w;
    }

    const float* Kb = g_K + (size_t)bh * Tc * Ec;
    for (int kt = 0; kt < ntiles; kt++) {
        __syncthreads();
        for (int idx = tid; idx < 64 * 16; idx += 256) {
            int c = idx >> 4, e4 = (idx & 15) * 4;
            float4 v = *(const float4*)(Kb + (size_t)(kt * 64 + c) * Ec + e4);
            KTd(c, e4 + 0) = v.x; KTd(c, e4 + 1) = v.y;
            KTd(c, e4 + 2) = v.z; KTd(c, e4 + 3) = v.w;
        }
        __syncthreads();
        float acc[2][2];
        #pragma unroll
        for (int i = 0; i < 2; i++) { acc[i][0] = 0.f; acc[i][1] = 0.f; }
        #pragma unroll 4
        for (int e = 0; e < 64; e++) {
            float kv0 = KTd(lane, e), kv1 = KTd(lane + 32, e);
            #pragma unroll
            for (int i = 0; i < 2; i++) {
                float qv = QSd(ty * 2 + i, e);
                acc[i][0] += qv * kv0;
                acc[i][1] += qv * kv1;
            }
        }
        #pragma unroll
        for (int i = 0; i < 2; i++) {
            int rl = ty * 2 + i, r = r0 + rl;
            int c0 = kt * 64 + lane, c1 = c0 + 32;
            if (c0 <= r) SCD(rl, c0) = acc[i][0] * 0.125f;
            if (c1 <= r) SCD(rl, c1) = acc[i][1] * 0.125f;
        }
    }
    __syncthreads();

    #pragma unroll
    for (int it = 0; it < 2; it++) {
        int rl = it * 8 + ty, r = r0 + rl, n = r + 1;
        float m = -1e30f;
        for (int c = lane; c < n; c += 32) m = fmaxf(m, SCD(rl, c));
        #pragma unroll
        for (int off = 16; off; off >>= 1)
            m = fmaxf(m, __shfl_xor_sync(0xffffffffu, m, off));
        float sum = 0.f;
        for (int c = lane; c < n; c += 32) {
            float e = __expf(SCD(rl, c) - m);
            SCD(rl, c) = e;
            sum += e;
        }
        #pragma unroll
        for (int off = 16; off; off >>= 1)
            sum += __shfl_xor_sync(0xffffffffu, sum, off);
        float inv = __fdividef(1.f, sum);
        float* wrow = wout_base + ((size_t)bh * Tc + r) * Tc;
        for (int c = lane; c < Tc; c += 32) {
            float v = 0.f;
            if (c < n) { v = SCD(rl, c) * inv; SCD(rl, c) = v; }
            __stwt(&wrow[c], v);
        }
    }
    __syncthreads();

    const float* Vb = g_V + (size_t)bh * Tc * Ec;
    float oacc[2][2];
    #pragma unroll
    for (int i = 0; i < 2; i++) { oacc[i][0] = 0.f; oacc[i][1] = 0.f; }
    for (int kt = 0; kt < ntiles; kt++) {
        __syncthreads();
        for (int idx = tid; idx < 64 * 16; idx += 256) {
            int c = idx >> 4, e4 = (idx & 15) * 4;
            float4 v = *(const float4*)(Vb + (size_t)(kt * 64 + c) * Ec + e4);
            KTd(c, e4 + 0) = v.x; KTd(c, e4 + 1) = v.y;
            KTd(c, e4 + 2) = v.z; KTd(c, e4 + 3) = v.w;
        }
        __syncthreads();
        #pragma unroll 4
        for (int c = 0; c < 64; c++) {
            float v0 = KTd(c, lane), v1 = KTd(c, lane + 32);
            #pragma unroll
            for (int i = 0; i < 2; i++) {
                float wg = SCD(ty * 2 + i, kt * 64 + c);
                oacc[i][0] += wg * v0;
                oacc[i][1] += wg * v1;
            }
        }
    }
    #pragma unroll
    for (int i = 0; i < 2; i++) {
        float* dst = g_ATT + ((size_t)bh * Tc + r0 + ty * 2 + i) * Ec;
        dst[lane] = oacc[i][0];
        dst[lane + 32] = oacc[i][1];
    }
}

// ===========================================================================
// Sparse attention (rows >= 384): one warp per row; unroll-8 score loop
// (R11 measured-best); early-out coalesced weight writes.
// Grid: x = bh, y = row-group  ->  heaviest groups of ALL bh launch first.
// ===========================================================================
__global__ __launch_bounds__(256) void attn_sparse(float* __restrict__ wout_base) {
    __shared__ float sc[8][CAP];
    int w = threadIdx.x >> 5;
    int lane = threadIdx.x & 31;
    int sub = lane & 7;
    int grp = lane >> 3;
    int r = 2047 - (blockIdx.y * 8 + w);
    int bh = blockIdx.x;

    const float* Qrow = g_Q + ((size_t)bh * Tc + r) * Ec;
    float4 qa4 = *(const float4*)(Qrow + sub * 4);
    float4 qb4 = *(const float4*)(Qrow + 32 + sub * 4);
    float2 qa = make_float2(qa4.x, qa4.y), qb = make_float2(qa4.z, qa4.w);
    float2 qc = make_float2(qb4.x, qb4.y), qd = make_float2(qb4.z, qb4.w);

    int cnt = g_cnt[r];
    const unsigned short* cl = g_cols + r * CAP;
    const float* Kb = g_K + (size_t)bh * Tc * Ec;
    const float2 zero2 = make_float2(0.f, 0.f);

    float m = -1e30f;
    int j0 = 0;
    for (; j0 + 8 <= cnt; j0 += 8) {
        int cA = cl[j0 + grp];
        int cB = cl[j0 + 4 + grp];
        const float* krA = Kb + (size_t)cA * Ec;
        const float* krB = Kb + (size_t)cB * Ec;
        float4 a0 = *(const float4*)(krA + sub * 4);
        float4 a1 = *(const float4*)(krA + 32 + sub * 4);
        float4 b0 = *(const float4*)(krB + sub * 4);
        float4 b1 = *(const float4*)(krB + 32 + sub * 4);
        float2 sA = ffma2(qa, make_float2(a0.x, a0.y), zero2);
        float2 sB = ffma2(qa, make_float2(b0.x, b0.y), zero2);
        sA = ffma2(qb, make_float2(a0.z, a0.w), sA);
        sB = ffma2(qb, make_float2(b0.z, b0.w), sB);
        sA = ffma2(qc, make_float2(a1.x, a1.y), sA);
        sB = ffma2(qc, make_float2(b1.x, b1.y), sB);
        sA = ffma2(qd, make_float2(a1.z, a1.w), sA);
        sB = ffma2(qd, make_float2(b1.z, b1.w), sB);
        float pA = sA.x + sA.y, pB = sB.x + sB.y;
        pA += __shfl_down_sync(0xffffffffu, pA, 4);
        pB += __shfl_down_sync(0xffffffffu, pB, 4);
        pA += __shfl_down_sync(0xffffffffu, pA, 2);
        pB += __shfl_down_sync(0xffffffffu, pB, 2);
        pA += __shfl_down_sync(0xffffffffu, pA, 1);
        pB += __shfl_down_sync(0xffffffffu, pB, 1);
        if (sub == 0) {
            float vA = pA * 0.125f, vB = pB * 0.125f;
            sc[w][j0 + grp] = vA;
            sc[w][j0 + 4 + grp] = vB;
            m = fmaxf(m, fmaxf(vA, vB));
        }
    }
    for (; j0 < cnt; j0 += 4) {
        int jj = j0 + grp;
        int c = cl[jj < cnt ? jj : cnt - 1];
        const float* krow = Kb + (size_t)c * Ec;
        float4 ka4 = *(const float4*)(krow + sub * 4);
        float4 kb4 = *(const float4*)(krow + 32 + sub * 4);
        float2 s2 = ffma2(qa, make_float2(ka4.x, ka4.y), zero2);
        s2 = ffma2(qb, make_float2(ka4.z, ka4.w), s2);
        s2 = ffma2(qc, make_float2(kb4.x, kb4.y), s2);
        s2 = ffma2(qd, make_float2(kb4.z, kb4.w), s2);
        float p = s2.x + s2.y;
        p += __shfl_down_sync(0xffffffffu, p, 4);
        p += __shfl_down_sync(0xffffffffu, p, 2);
        p += __shfl_down_sync(0xffffffffu, p, 1);
        float s = p * 0.125f;
        if (sub == 0 && jj < cnt) {
            sc[w][jj] = s;
            m = fmaxf(m, s);
        }
    }
    #pragma unroll
    for (int off = 16; off; off >>= 1)
        m = fmaxf(m, __shfl_xor_sync(0xffffffffu, m, off));
    __syncwarp();

    float sum = 0.f;
    for (int jj = lane; jj < cnt; jj += 32) {
        float e = __expf(sc[w][jj] - m);
        sc[w][jj] = e;
        sum += e;
    }
    #pragma unroll
    for (int off = 16; off; off >>= 1)
        sum += __shfl_xor_sync(0xffffffffu, sum, off);
    float inv = __fdividef(1.f, sum);
    __syncwarp();

    // coalesced full-row weight writes: predicate eval only at/below diagonal
    {
        int jl = r & 63;
        int nch = r >> 6;
        float* wrow = wout_base + ((size_t)bh * Tc + r) * Tc;
        const float4 z4 = make_float4(0.f, 0.f, 0.f, 0.f);
        for (int idx = lane; idx < 512; idx += 32) {
            int c0 = idx * 4;
            if (c0 > r) {                 // entirely above diagonal: pure zero
                __stwt(&((float4*)wrow)[idx], z4);
                continue;
            }
            float4 o = z4;
            #pragma unroll
            for (int jq = 0; jq < 4; jq++) {
                int c = c0 + jq;
                int diff = r - c;
                if (diff >= 0) {
                    int s = diff & 63;
                    if (((REMMASK >> s) & 1ull) && !(jl < 5 && c == jl)) {
                        int k = diff >> 6;
                        int jj = cnt - 1 - 12 * k - rank_of(s)
                                 + ((jl < 5 && k == nch) ? 1 : 0);
                        ((float*)&o)[jq] = sc[w][jj] * inv;
                    }
                }
            }
            __stwt(&((float4*)wrow)[idx], o);
        }
    }

    const float* Vb = g_V + (size_t)bh * Tc * Ec;
    float2 oacc = zero2, oacc2 = zero2;
    int jj = 0;
    for (; jj + 8 <= cnt; jj += 8) {
        float2 v[8];
        #pragma unroll
        for (int u = 0; u < 8; u++)
            v[u] = ((const float2*)(Vb + (size_t)cl[jj + u] * Ec))[lane];
        #pragma unroll
        for (int u = 0; u < 8; u += 2) {
            float w0 = sc[w][jj + u], w1 = sc[w][jj + u + 1];
            oacc  = ffma2(make_float2(w0, w0), v[u], oacc);
            oacc2 = ffma2(make_float2(w1, w1), v[u + 1], oacc2);
        }
    }
    for (; jj < cnt; jj++) {
        float wg = sc[w][jj];
        float2 v2 = ((const float2*)(Vb + (size_t)cl[jj] * Ec))[lane];
        oacc = ffma2(make_float2(wg, wg), v2, oacc);
    }
    float* ar = g_ATT + ((size_t)bh * Tc + r) * Ec;
    ((float2*)ar)[lane] = make_float2((oacc.x + oacc2.x) * inv,
                                      (oacc.y + oacc2.y) * inv);
}

// ===========================================================================
// Output projection: 32bt x 64eo block GEMM (unchanged)
// ===========================================================================
__global__ __launch_bounds__(256) void proj_out2(const float* __restrict__ Wp,
                                                 const float* __restrict__ bp,
                                                 float* __restrict__ out) {
    __shared__ float asT[64][36];
    __shared__ float wp[64][68];
    int bt0 = blockIdx.x * 32;
    int b = bt0 / Tc, t0 = bt0 & (Tc - 1);
    int tid = threadIdx.x;
    int ex = tid & 15;
    int mx = tid >> 4;

    float2 acc2[2][2];
    acc2[0][0] = make_float2(0.f,0.f); acc2[0][1] = make_float2(0.f,0.f);
    acc2[1][0] = make_float2(0.f,0.f); acc2[1][1] = make_float2(0.f,0.f);

    for (int cc = 0; cc < 8; cc++) {
        __syncthreads();
        for (int idx = tid; idx < 32 * 16; idx += 256) {
            int m = idx >> 4, e4 = (idx & 15) * 4;
            float4 v = *(const float4*)(g_ATT +
                (((size_t)b * Hc + cc) * Tc + t0 + m) * Ec + e4);
            asT[e4 + 0][m] = v.x; asT[e4 + 1][m] = v.y;
            asT[e4 + 2][m] = v.z; asT[e4 + 3][m] = v.w;
        }
        for (int idx = tid; idx < 64 * 16; idx += 256) {
            int k = idx >> 4, e4 = (idx & 15) * 4;
            *(float4*)&wp[k][e4] =
                *(const float4*)(Wp + (size_t)(cc * 64 + k) * Ec + e4);
        }
        __syncthreads();
        #pragma unroll 8
        for (int k = 0; k < 64; k++) {
            float2 a2 = *(float2*)&asT[k][mx * 2];
            float4 w4 = *(float4*)&wp[k][ex * 4];
            float2 wp0 = make_float2(w4.x, w4.y);
            float2 wp1 = make_float2(w4.z, w4.w);
            float2 xb0 = make_float2(a2.x, a2.x);
            float2 xb1 = make_float2(a2.y, a2.y);
            acc2[0][0] = ffma2(xb0, wp0, acc2[0][0]);
            acc2[0][1] = ffma2(xb0, wp1, acc2[0][1]);
            acc2[1][0] = ffma2(xb1, wp0, acc2[1][0]);
            acc2[1][1] = ffma2(xb1, wp1, acc2[1][1]);
        }
    }
    float4 bp4 = *(const float4*)(bp + ex * 4);
    #pragma unroll
    for (int u = 0; u < 2; u++) {
        int t = t0 + mx * 2 + u;
        float4 o = make_float4(acc2[u][0].x + bp4.x, acc2[u][0].y + bp4.y,
                               acc2[u][1].x + bp4.z, acc2[u][1].y + bp4.w);
        *(float4*)(out + ((size_t)b * Tc + t) * Ec + ex * 4) = o;
    }
}

// ---------------------------------------------------------------------------
extern "C" void kernel_launch(void* const* d_in, const int* in_sizes, int n_in,
                              void* d_out, int out_size) {
    const float* x    = (const float*)d_in[0];
    const float* Wqk  = (const float*)d_in[1];
    const float* bqk  = (const float*)d_in[2];
    const float* Wv   = (const float*)d_in[3];
    const float* bv   = (const float*)d_in[4];
    const float* Wp   = (const float*)d_in[5];
    const float* bp   = (const float*)d_in[6];
    // d_in[7] (mask) unused: regenerated on-device.

    float* out = (float*)d_out;
    float* weights = out + (size_t)Bc * Tc * Ec;

    const int DENSE_SMEM = (16 * 385 + 16 * 65 + 64 * 65) * 4;   // 45,440 B
    cudaFuncSetAttribute(dense_attn,
                         cudaFuncAttributeMaxDynamicSharedMemorySize, DENSE_SMEM);

    fat_prep<<<1416, 256>>>(x, Wv, bv, Wqk);
    proj_qk2<<<dim3(Tc / 64, 16, Bc), 256>>>(x, bqk);
    dense_attn<<<dim3(24, BHc), 256, DENSE_SMEM>>>(weights);
    attn_sparse<<<dim3(BHc, 208), 256>>>(weights);
    proj_out2<<<Bc * Tc / 32, 256>>>(Wp, bp, out);
}